// round 2
// baseline (speedup 1.0000x reference)
#include <cuda_runtime.h>

// x: (B=64, W=512, H=48, M=64) float32, row-major.
// out[b, iw*(6*64) + ih*64 + m] = max_{w in [32iw,32iw+32), h in [8ih,8ih+8)} x[b,w,h,m]
//
// Block: one (b, iw) tile. 384 threads = 4 w-splits x 96 (ih, m4) float4 outputs.
// Each thread: 8 w-rows x 8 h float4 loads (inner unrolled for MLP), then
// 4-way shared-memory max across w-splits.

#define NB 64
#define NW 512
#define NH 48
#define NM 64
#define PW 16
#define PH 6
// floats per (b,w) row = NH*NM = 3072 -> 768 float4
#define ROW_F4 768
// float4 per h step = NM/4 = 16
#define H_F4 16

__device__ __forceinline__ float4 f4max(float4 a, float4 b) {
    a.x = fmaxf(a.x, b.x);
    a.y = fmaxf(a.y, b.y);
    a.z = fmaxf(a.z, b.z);
    a.w = fmaxf(a.w, b.w);
    return a;
}

__global__ __launch_bounds__(384)
void dap_pool_kernel(const float4* __restrict__ x, float4* __restrict__ out) {
    const int blk = blockIdx.x;       // b*16 + iw
    const int b  = blk >> 4;
    const int iw = blk & 15;
    const int tid = threadIdx.x;      // 0..383
    const int ws  = tid / 96;         // w-split 0..3 (8 w-rows each)
    const int om  = tid - ws * 96;    // ih*16 + m4
    const int ih  = om >> 4;
    const int m4  = om & 15;

    // base float4 index of x[b, iw*32 + ws*8, ih*8, m4*4]
    const size_t base = ((size_t)(b * NW + iw * 32 + ws * 8) * NH + ih * 8) * H_F4 + m4;
    const float4* p = x + base;

    float4 acc = make_float4(-__FLT_MAX__, -__FLT_MAX__, -__FLT_MAX__, -__FLT_MAX__);

    #pragma unroll 1
    for (int wl = 0; wl < 8; wl++) {
        const float4* q = p + (size_t)wl * ROW_F4;
        float4 v0 = q[0 * H_F4];
        float4 v1 = q[1 * H_F4];
        float4 v2 = q[2 * H_F4];
        float4 v3 = q[3 * H_F4];
        float4 v4 = q[4 * H_F4];
        float4 v5 = q[5 * H_F4];
        float4 v6 = q[6 * H_F4];
        float4 v7 = q[7 * H_F4];
        v0 = f4max(v0, v1);
        v2 = f4max(v2, v3);
        v4 = f4max(v4, v5);
        v6 = f4max(v6, v7);
        v0 = f4max(v0, v2);
        v4 = f4max(v4, v6);
        acc = f4max(acc, f4max(v0, v4));
    }

    __shared__ float4 smem[384];
    smem[tid] = acc;
    __syncthreads();

    if (tid < 96) {
        float4 a = smem[tid];
        a = f4max(a, smem[tid + 96]);
        a = f4max(a, smem[tid + 192]);
        a = f4max(a, smem[tid + 288]);
        // out float4 index: b*(PW*PH*NM/4) + iw*(PH*NM/4) + tid
        out[(size_t)b * (PW * PH * (NM / 4)) + iw * (PH * (NM / 4)) + tid] = a;
    }
}

extern "C" void kernel_launch(void* const* d_in, const int* in_sizes, int n_in,
                              void* d_out, int out_size) {
    (void)in_sizes; (void)n_in; (void)out_size;
    const float4* x = (const float4*)d_in[0];
    float4* out = (float4*)d_out;
    dap_pool_kernel<<<NB * PW, 384>>>(x, out);
}

// round 4
// speedup vs baseline: 1.0414x; 1.0414x over previous
#include <cuda_runtime.h>

// x: (B=64, W=512, H=48, M=64) float32, row-major.
// out[b, iw*(6*64) + ih*64 + m] = max_{w in [32iw,32iw+32), h in [8ih,8ih+8)} x[b,w,h,m]
//
// Block: one (b, iw) tile. 384 threads = 4 w-splits x 96 (ih, m4) float4 outputs.
// Each thread: 8 w-rows x 8 h float4 streaming loads, w-loop unrolled by 2
// (16 LDG.E.CS.128 front-batched -> MLP 16), then 4-way shared max across splits.

#define NB 64
#define NW 512
#define NH 48
#define NM 64
#define PW 16
#define PH 6
#define ROW_F4 768   // float4 per (b,w) row = 48*64/4
#define H_F4 16      // float4 per h step

__device__ __forceinline__ float4 ld_cs(const float4* p) {
    float4 v;
    asm volatile("ld.global.cs.v4.f32 {%0,%1,%2,%3}, [%4];"
                 : "=f"(v.x), "=f"(v.y), "=f"(v.z), "=f"(v.w) : "l"(p));
    return v;
}

__device__ __forceinline__ float4 f4max(float4 a, float4 b) {
    a.x = fmaxf(a.x, b.x);
    a.y = fmaxf(a.y, b.y);
    a.z = fmaxf(a.z, b.z);
    a.w = fmaxf(a.w, b.w);
    return a;
}

__global__ __launch_bounds__(384, 2)
void dap_pool_kernel(const float4* __restrict__ x, float4* __restrict__ out) {
    const int blk = blockIdx.x;       // b*16 + iw
    const int b  = blk >> 4;
    const int iw = blk & 15;
    const int tid = threadIdx.x;      // 0..383
    const int ws  = tid / 96;         // w-split 0..3 (8 w-rows each)
    const int om  = tid - ws * 96;    // ih*16 + m4
    const int ih  = om >> 4;
    const int m4  = om & 15;

    // base float4 index of x[b, iw*32 + ws*8, ih*8, m4*4]
    const size_t base = ((size_t)(b * NW + iw * 32 + ws * 8) * NH + ih * 8) * H_F4 + m4;
    const float4* p = x + base;

    float4 acc = make_float4(-__FLT_MAX__, -__FLT_MAX__, -__FLT_MAX__, -__FLT_MAX__);

    #pragma unroll 1
    for (int wl = 0; wl < 8; wl += 2) {
        const float4* q0 = p + (size_t)wl * ROW_F4;
        const float4* q1 = q0 + ROW_F4;
        // 16 streaming loads batched for MLP=16
        float4 a0 = ld_cs(q0 + 0 * H_F4);
        float4 a1 = ld_cs(q0 + 1 * H_F4);
        float4 a2 = ld_cs(q0 + 2 * H_F4);
        float4 a3 = ld_cs(q0 + 3 * H_F4);
        float4 a4 = ld_cs(q0 + 4 * H_F4);
        float4 a5 = ld_cs(q0 + 5 * H_F4);
        float4 a6 = ld_cs(q0 + 6 * H_F4);
        float4 a7 = ld_cs(q0 + 7 * H_F4);
        float4 b0 = ld_cs(q1 + 0 * H_F4);
        float4 b1 = ld_cs(q1 + 1 * H_F4);
        float4 b2 = ld_cs(q1 + 2 * H_F4);
        float4 b3 = ld_cs(q1 + 3 * H_F4);
        float4 b4 = ld_cs(q1 + 4 * H_F4);
        float4 b5 = ld_cs(q1 + 5 * H_F4);
        float4 b6 = ld_cs(q1 + 6 * H_F4);
        float4 b7 = ld_cs(q1 + 7 * H_F4);

        a0 = f4max(a0, b0);
        a1 = f4max(a1, b1);
        a2 = f4max(a2, b2);
        a3 = f4max(a3, b3);
        a4 = f4max(a4, b4);
        a5 = f4max(a5, b5);
        a6 = f4max(a6, b6);
        a7 = f4max(a7, b7);
        a0 = f4max(a0, a1);
        a2 = f4max(a2, a3);
        a4 = f4max(a4, a5);
        a6 = f4max(a6, a7);
        a0 = f4max(a0, a2);
        a4 = f4max(a4, a6);
        acc = f4max(acc, f4max(a0, a4));
    }

    __shared__ float4 smem[384];
    smem[tid] = acc;
    __syncthreads();

    if (tid < 96) {
        float4 a = smem[tid];
        a = f4max(a, smem[tid + 96]);
        a = f4max(a, smem[tid + 192]);
        a = f4max(a, smem[tid + 288]);
        out[(size_t)b * (PW * PH * (NM / 4)) + iw * (PH * (NM / 4)) + tid] = a;
    }
}

extern "C" void kernel_launch(void* const* d_in, const int* in_sizes, int n_in,
                              void* d_out, int out_size) {
    (void)in_sizes; (void)n_in; (void)out_size;
    const float4* x = (const float4*)d_in[0];
    float4* out = (float4*)d_out;
    dap_pool_kernel<<<NB * PW, 384>>>(x, out);
}